// round 15
// baseline (speedup 1.0000x reference)
#include <cuda_runtime.h>
#include <cuda_fp16.h>
#include <math.h>
#include <stdint.h>

// Problem constants
#define BB   4
#define SS   2048
#define DD   768
#define HH   12
#define DFF  3072
#define MR   8192          // B*S
#define EPSL 1e-5f

#define SZ_D   (MR * DD)
#define SZ_FF  (MR * DFF)
#define SZ_W   (DD * DD)
#define SZ_W1  (DD * DFF)

// ---------------- scratch ----------------------------------------------------
static __device__ __align__(256) __half g_half[8 * SZ_D + SZ_FF + 4 * SZ_W + 2 * SZ_W1];
static __device__ __align__(256) float g_x1[SZ_D];

#define HO_QR   0
#define HO_KR   (HO_QR + SZ_D)
#define HO_VR   (HO_KR + SZ_D)
#define HO_GQ   (HO_VR + SZ_D)
#define HO_GK   (HO_GQ + SZ_D)
#define HO_GV   (HO_GK + SZ_D)
#define HO_CTX  (HO_GV + SZ_D)
#define HO_H    (HO_CTX + SZ_D)
#define HO_FF   (HO_H + SZ_D)
#define HO_WQ   (HO_FF + SZ_FF)
#define HO_WK   (HO_WQ + SZ_W)
#define HO_WV   (HO_WK + SZ_W)
#define HO_WO   (HO_WV + SZ_W)
#define HO_W1   (HO_WO + SZ_W)
#define HO_W2   (HO_W1 + SZ_W1)

// ---------------- helpers ----------------------------------------------------
__device__ __forceinline__ float gelu_exact(float x) {
    return 0.5f * x * (1.0f + erff(x * 0.70710678118654752f));
}

__device__ __forceinline__ void cpa16(uint32_t s, const void* g) {
    asm volatile("cp.async.cg.shared.global [%0], [%1], 16;" :: "r"(s), "l"(g));
}

__device__ __forceinline__ uint32_t smem_u32(const void* p) {
    uint32_t a;
    asm("{ .reg .u64 t; cvta.to.shared.u64 t, %1; cvt.u32.u64 %0, t; }"
        : "=r"(a) : "l"(p));
    return a;
}

#define LDSM4(r0, r1, r2, r3, addr)                                            \
    asm volatile("ldmatrix.sync.aligned.m8n8.x4.shared.b16 {%0,%1,%2,%3}, [%4];" \
        : "=r"(r0), "=r"(r1), "=r"(r2), "=r"(r3) : "r"(addr))

#define LDSM4T(r0, r1, r2, r3, addr)                                           \
    asm volatile("ldmatrix.sync.aligned.m8n8.x4.trans.shared.b16 {%0,%1,%2,%3}, [%4];" \
        : "=r"(r0), "=r"(r1), "=r"(r2), "=r"(r3) : "r"(addr))

// fp16 warp MMA: D(16x8,f32) += A(16x16,f16) * B(16x8,f16)
__device__ __forceinline__ void mma16(float* c, const uint32_t* a, const uint32_t* b) {
    asm volatile(
        "mma.sync.aligned.m16n8k16.row.col.f32.f16.f16.f32 "
        "{%0,%1,%2,%3}, {%4,%5,%6,%7}, {%8,%9}, {%0,%1,%2,%3};"
        : "+f"(c[0]), "+f"(c[1]), "+f"(c[2]), "+f"(c[3])
        : "r"(a[0]), "r"(a[1]), "r"(a[2]), "r"(a[3]), "r"(b[0]), "r"(b[1]));
}

__device__ __forceinline__ uint32_t pack2h(float lo, float hi) {
    __half2 h = __floats2half2_rn(lo, hi);
    return *(uint32_t*)&h;
}

// ---------------- merged pre-pass: fp32 -> fp16, 9 segments ------------------
struct Seg  { const float* s; __half* d; };
struct Segs { Seg g[9]; int cum[10]; };

__global__ __launch_bounds__(256) void f2h_multi(Segs S)
{
    const int base = blockIdx.x * 256;
    int seg = 0;
#pragma unroll
    for (int j = 1; j < 9; ++j)
        if (base >= S.cum[j]) seg = j;
    const int i = base - S.cum[seg] + threadIdx.x;
    const float4 v = ((const float4*)S.g[seg].s)[i];
    uint2 o;
    o.x = pack2h(v.x, v.y);
    o.y = pack2h(v.z, v.w);
    ((uint2*)S.g[seg].d)[i] = o;
}

// ---------------- fp16 mma GEMM (unchanged from R10) -------------------------
struct GSet { const __half* A; const __half* Bm; const float* bias;
              const float* res; void* C; };
struct GSet3 { GSet s[3]; };

#define APADH 24
#define NSTG  4

template <int CTAM, int CTAN, int EPI, int OUTH>
__global__ __launch_bounds__((CTAN == 256) ? 256 : 128, (CTAN == 256) ? 1 : 3)
void hgemm(GSet3 P, int M, int N, int K)
{
    constexpr int T     = (CTAN == 256) ? 256 : 128;
    constexpr int MT    = CTAM / 32;
    constexpr int BPADH = CTAN + 8;
    constexpr int ASTG  = CTAM * APADH;
    constexpr int BSTG  = 16 * BPADH;
    constexpr int NQ    = CTAN / 8;

    extern __shared__ __half hsm[];
    __half* As = hsm;
    __half* Bs = hsm + NSTG * ASTG;

    const GSet gs = P.s[blockIdx.z];
    const __half* __restrict__ A = gs.A;
    const __half* __restrict__ Bm = gs.Bm;
    const float* __restrict__ bias = gs.bias;
    const float* __restrict__ res = gs.res;

    const int tid = threadIdx.x;
    const int wid = tid >> 5;
    const int lane = tid & 31;
    const int wm = wid & 1;
    const int wn = wid >> 1;

    const int bm = blockIdx.y * CTAM;
    const int bn = blockIdx.x * CTAN;

    float acc[MT][8][4];
#pragma unroll
    for (int i = 0; i < MT; ++i)
#pragma unroll
        for (int j = 0; j < 8; ++j)
#pragma unroll
            for (int q = 0; q < 4; ++q) acc[i][j][q] = 0.0f;

    const uint32_t sAb = smem_u32(As);
    const uint32_t sBb = smem_u32(Bs);

    const int KT = K >> 4;

    auto load_stage = [&](int kt) {
        const int st = kt & 3;
        const int k0 = kt << 4;
        const uint32_t aB = sAb + (uint32_t)st * ASTG * 2u;
        const uint32_t bB = sBb + (uint32_t)st * BSTG * 2u;
        {
            const int m = tid >> 1, hc = (tid & 1) * 8;
            cpa16(aB + (uint32_t)(m * APADH + hc) * 2u,
                  A + (size_t)(bm + m) * K + k0 + hc);
        }
#pragma unroll
        for (int i = 0; i < 2; ++i) {
            const int c = tid + i * T;
            const int kr = c / NQ, nq = c % NQ;
            cpa16(bB + (uint32_t)(kr * BPADH + nq * 8) * 2u,
                  Bm + (size_t)(k0 + kr) * N + bn + nq * 8);
        }
        asm volatile("cp.async.commit_group;" ::: "memory");
    };

    load_stage(0); load_stage(1); load_stage(2);

    for (int kt = 0; kt < KT; ++kt) {
        const int rem = KT - 1 - kt;
        if (rem >= 2)      asm volatile("cp.async.wait_group 2;" ::: "memory");
        else if (rem == 1) asm volatile("cp.async.wait_group 1;" ::: "memory");
        else               asm volatile("cp.async.wait_group 0;" ::: "memory");
        __syncthreads();
        if (kt + 3 < KT) load_stage(kt + 3);

        const int st = kt & 3;
        const uint32_t aS = sAb + (uint32_t)st * ASTG * 2u;
        const uint32_t bS = sBb + (uint32_t)st * BSTG * 2u;

        uint32_t au[MT][4], bu[8][2];
#pragma unroll
        for (int mt = 0; mt < MT; ++mt) {
            const int row = wm * (CTAM / 2) + mt * 16 + (lane & 15);
            const int kh = (lane >> 4) * 8;
            LDSM4(au[mt][0], au[mt][1], au[mt][2], au[mt][3],
                  aS + (uint32_t)(row * APADH + kh) * 2u);
        }
#pragma unroll
        for (int ng = 0; ng < 4; ++ng) {
            const int n0 = wn * 64 + ng * 16;
            const uint32_t ad = bS +
                (uint32_t)((lane & 15) * BPADH + n0 + (lane >> 4) * 8) * 2u;
            LDSM4T(bu[2 * ng][0], bu[2 * ng][1],
                   bu[2 * ng + 1][0], bu[2 * ng + 1][1], ad);
        }
#pragma unroll
        for (int mt = 0; mt < MT; ++mt)
#pragma unroll
            for (int nt = 0; nt < 8; ++nt)
                mma16(acc[mt][nt], au[mt], bu[nt]);
    }

#pragma unroll
    for (int mt = 0; mt < MT; ++mt) {
        const int r0 = bm + wm * (CTAM / 2) + mt * 16 + (lane >> 2);
#pragma unroll
        for (int nt = 0; nt < 8; ++nt) {
            const int col = bn + wn * 64 + nt * 8 + (lane & 3) * 2;
            const float b0 = bias[col], b1 = bias[col + 1];
            float v0 = acc[mt][nt][0] + b0;
            float v1 = acc[mt][nt][1] + b1;
            float v2 = acc[mt][nt][2] + b0;
            float v3 = acc[mt][nt][3] + b1;
            if (EPI == 1) {
                const float2 ra = *(const float2*)&res[(size_t)r0 * N + col];
                const float2 rb = *(const float2*)&res[(size_t)(r0 + 8) * N + col];
                v0 += ra.x; v1 += ra.y; v2 += rb.x; v3 += rb.y;
            }
            if (EPI == 2) {
                v0 = gelu_exact(v0); v1 = gelu_exact(v1);
                v2 = gelu_exact(v2); v3 = gelu_exact(v3);
            }
            if (OUTH) {
                __half* C = (__half*)gs.C;
                *(uint32_t*)&C[(size_t)r0 * N + col] = pack2h(v0, v1);
                *(uint32_t*)&C[(size_t)(r0 + 8) * N + col] = pack2h(v2, v3);
            } else {
                float* C = (float*)gs.C;
                *(float2*)&C[(size_t)r0 * N + col] = make_float2(v0, v1);
                *(float2*)&C[(size_t)(r0 + 8) * N + col] = make_float2(v2, v3);
            }
        }
    }
}

#define GEMM_SMEM_W ((NSTG * (128 * APADH + 16 * (256 + 8))) * 2)
#define GEMM_SMEM_N ((NSTG * (64 * APADH + 16 * (128 + 8))) * 2)

// ---------------- fp16 flash attention: occ 2, split K/V waits ---------------
#define KPADH 72
#define ATTN_SMEM ((128 * KPADH + 2 * 64 * KPADH + 2 * 64 * KPADH) * 2)

__global__ __launch_bounds__(256, 2) void attn_h(
    const __half* __restrict__ q, const __half* __restrict__ k,
    const __half* __restrict__ v, __half* __restrict__ ctx)
{
    extern __shared__ __half asm_[];
    __half* Qs = asm_;                        // [128][72]
    __half* Ks = Qs + 128 * KPADH;            // [2][64][72]
    __half* Vs = Ks + 2 * 64 * KPADH;         // [2][64][72]

    const int bh = blockIdx.x;
    const int qt = blockIdx.y;
    const int b = bh / HH, h = bh % HH;
    const int tid = threadIdx.x;
    const int wid = tid >> 5;
    const int lane = tid & 31;
    const size_t base = (size_t)(b * SS) * DD + h * 64;
    const int q0 = qt * 128;
    const int NT = SS / 64;

    // stage Q
#pragma unroll
    for (int i = 0; i < 4; ++i) {
        const int idx = tid + i * 256;
        const int r = idx >> 3, hc = idx & 7;
        cpa16(smem_u32(Qs + r * KPADH + hc * 8),
              q + base + (size_t)(q0 + r) * DD + hc * 8);
    }
    asm volatile("cp.async.commit_group; cp.async.wait_group 0;" ::: "memory");
    __syncthreads();

    // Q fragments, scaled by 1/8
    uint32_t qf[4][4];
    {
        const int row = wid * 16 + (lane & 15);
        const __half2 s8 = __float2half2_rn(0.125f);
#pragma unroll
        for (int dk = 0; dk < 4; ++dk) {
            LDSM4(qf[dk][0], qf[dk][1], qf[dk][2], qf[dk][3],
                  smem_u32(Qs + row * KPADH + dk * 16 + (lane >> 4) * 8));
#pragma unroll
            for (int j = 0; j < 4; ++j) {
                __half2 t = __hmul2(*(__half2*)&qf[dk][j], s8);
                qf[dk][j] = *(uint32_t*)&t;
            }
        }
    }

    float oacc[8][4];
#pragma unroll
    for (int nt = 0; nt < 8; ++nt)
#pragma unroll
        for (int i = 0; i < 4; ++i) oacc[nt][i] = 0.0f;
    float m0 = -INFINITY, m1 = -INFINITY, l0 = 0.0f, l1 = 0.0f;

    // prefetch: K and V in SEPARATE commit groups (K first)
    auto prefetch = [&](int t) {
        const int buf = t & 1;
#pragma unroll
        for (int i = 0; i < 2; ++i) {
            const int idx = tid + i * 256;
            const int r = idx >> 3, hc = idx & 7;
            cpa16(smem_u32(Ks + (buf * 64 + r) * KPADH + hc * 8),
                  k + base + (size_t)(t * 64 + r) * DD + hc * 8);
        }
        asm volatile("cp.async.commit_group;" ::: "memory");
#pragma unroll
        for (int i = 0; i < 2; ++i) {
            const int idx = tid + i * 256;
            const int r = idx >> 3, hc = idx & 7;
            cpa16(smem_u32(Vs + (buf * 64 + r) * KPADH + hc * 8),
                  v + base + (size_t)(t * 64 + r) * DD + hc * 8);
        }
        asm volatile("cp.async.commit_group;" ::: "memory");
    };

    prefetch(0);

    for (int t = 0; t < NT; ++t) {
        // K(t) ready (V(t) may still be in flight)
        asm volatile("cp.async.wait_group 1;" ::: "memory");
        __syncthreads();                       // all warps done with buffer t-1
        const bool more = (t + 1 < NT);
        if (more) prefetch(t + 1);             // commits K(t+1), V(t+1)

        const uint32_t kb = smem_u32(Ks + (t & 1) * 64 * KPADH);
        const uint32_t vb = smem_u32(Vs + (t & 1) * 64 * KPADH);

        // S = Q K^T
        float sacc[8][4];
#pragma unroll
        for (int nt = 0; nt < 8; ++nt)
#pragma unroll
            for (int i = 0; i < 4; ++i) sacc[nt][i] = 0.0f;

#pragma unroll
        for (int dk = 0; dk < 4; ++dk) {
            uint32_t ku[8][2];
#pragma unroll
            for (int cg = 0; cg < 4; ++cg) {
                const int row = cg * 16 + (lane & 7) + ((lane >> 4) * 8);
                const int dh = dk * 16 + ((lane >> 3) & 1) * 8;
                LDSM4(ku[2 * cg][0], ku[2 * cg][1],
                      ku[2 * cg + 1][0], ku[2 * cg + 1][1],
                      kb + (uint32_t)(row * KPADH + dh) * 2u);
            }
#pragma unroll
            for (int ct = 0; ct < 8; ++ct) mma16(sacc[ct], qf[dk], ku[ct]);
        }

        // online softmax
        float mx0 = -INFINITY, mx1 = -INFINITY;
#pragma unroll
        for (int nt = 0; nt < 8; ++nt) {
            mx0 = fmaxf(mx0, fmaxf(sacc[nt][0], sacc[nt][1]));
            mx1 = fmaxf(mx1, fmaxf(sacc[nt][2], sacc[nt][3]));
        }
        mx0 = fmaxf(mx0, __shfl_xor_sync(0xffffffffu, mx0, 1));
        mx0 = fmaxf(mx0, __shfl_xor_sync(0xffffffffu, mx0, 2));
        mx1 = fmaxf(mx1, __shfl_xor_sync(0xffffffffu, mx1, 1));
        mx1 = fmaxf(mx1, __shfl_xor_sync(0xffffffffu, mx1, 2));

        const float mn0 = fmaxf(m0, mx0), mn1 = fmaxf(m1, mx1);
        const float cor0 = __expf(m0 - mn0), cor1 = __expf(m1 - mn1);
        float rs0 = 0.0f, rs1 = 0.0f;
#pragma unroll
        for (int nt = 0; nt < 8; ++nt) {
            sacc[nt][0] = __expf(sacc[nt][0] - mn0);
            sacc[nt][1] = __expf(sacc[nt][1] - mn0);
            sacc[nt][2] = __expf(sacc[nt][2] - mn1);
            sacc[nt][3] = __expf(sacc[nt][3] - mn1);
            rs0 += sacc[nt][0] + sacc[nt][1];
            rs1 += sacc[nt][2] + sacc[nt][3];
        }
        rs0 += __shfl_xor_sync(0xffffffffu, rs0, 1);
        rs0 += __shfl_xor_sync(0xffffffffu, rs0, 2);
        rs1 += __shfl_xor_sync(0xffffffffu, rs1, 1);
        rs1 += __shfl_xor_sync(0xffffffffu, rs1, 2);

        l0 = l0 * cor0 + rs0;
        l1 = l1 * cor1 + rs1;
        m0 = mn0; m1 = mn1;
#pragma unroll
        for (int nt = 0; nt < 8; ++nt) {
            oacc[nt][0] *= cor0; oacc[nt][1] *= cor0;
            oacc[nt][2] *= cor1; oacc[nt][3] *= cor1;
        }

        // V(t) ready: if prefetch(t+1) issued, 2 newer groups outstanding
        if (more) { asm volatile("cp.async.wait_group 2;" ::: "memory"); }
        else      { asm volatile("cp.async.wait_group 0;" ::: "memory"); }

        // O += P V  (P in registers)
#pragma unroll
        for (int cc = 0; cc < 4; ++cc) {
            uint32_t af[4];
            af[0] = pack2h(sacc[2 * cc][0], sacc[2 * cc][1]);
            af[1] = pack2h(sacc[2 * cc][2], sacc[2 * cc][3]);
            af[2] = pack2h(sacc[2 * cc + 1][0], sacc[2 * cc + 1][1]);
            af[3] = pack2h(sacc[2 * cc + 1][2], sacc[2 * cc + 1][3]);

            uint32_t vu[8][2];
#pragma unroll
            for (int dg = 0; dg < 4; ++dg) {
                const int row = cc * 16 + (lane & 15);
                const int dh = dg * 16 + (lane >> 4) * 8;
                LDSM4T(vu[2 * dg][0], vu[2 * dg][1],
                       vu[2 * dg + 1][0], vu[2 * dg + 1][1],
                       vb + (uint32_t)(row * KPADH + dh) * 2u);
            }
#pragma unroll
            for (int dt = 0; dt < 8; ++dt) mma16(oacc[dt], af, vu[dt]);
        }
    }

    const float inv0 = 1.0f / l0, inv1 = 1.0f / l1;
    const int row0 = wid * 16 + (lane >> 2);
#pragma unroll
    for (int dt = 0; dt < 8; ++dt) {
        const int col = dt * 8 + (lane & 3) * 2;
        *(uint32_t*)(ctx + base + (size_t)(q0 + row0) * DD + col) =
            pack2h(oacc[dt][0] * inv0, oacc[dt][1] * inv0);
        *(uint32_t*)(ctx + base + (size_t)(q0 + row0 + 8) * DD + col) =
            pack2h(oacc[dt][2] * inv1, oacc[dt][3] * inv1);
    }
}

// ---------------- layernorm: fp32 in, half out -------------------------------
__global__ __launch_bounds__(256) void ln_kernel(
    const float* __restrict__ x, const float* __restrict__ g,
    const float* __restrict__ bta, __half* __restrict__ y)
{
    const int row = blockIdx.x;
    const float* xr = x + (size_t)row * DD;
    const int tid = threadIdx.x;
    const int lane = tid & 31;
    const int wid = tid >> 5;

    float vals[3];
#pragma unroll
    for (int i = 0; i < 3; ++i) vals[i] = xr[tid + i * 256];

    __shared__ float red[32];

    float sum = vals[0] + vals[1] + vals[2];
#pragma unroll
    for (int off = 16; off >= 1; off >>= 1)
        sum += __shfl_xor_sync(0xffffffffu, sum, off);
    if (lane == 0) red[wid] = sum;
    __syncthreads();
    if (tid < 32) {
        float t = (lane < 8) ? red[lane] : 0.0f;
#pragma unroll
        for (int off = 4; off >= 1; off >>= 1)
            t += __shfl_xor_sync(0xffffffffu, t, off);
        if (lane == 0) red[0] = t * (1.0f / DD);
    }
    __syncthreads();
    const float mu = red[0];
    __syncthreads();

    float vs = 0.0f;
#pragma unroll
    for (int i = 0; i < 3; ++i) {
        const float d = vals[i] - mu;
        vs += d * d;
    }
#pragma unroll
    for (int off = 16; off >= 1; off >>= 1)
        vs += __shfl_xor_sync(0xffffffffu, vs, off);
    if (lane == 0) red[wid] = vs;
    __syncthreads();
    if (tid < 32) {
        float t = (lane < 8) ? red[lane] : 0.0f;
#pragma unroll
        for (int off = 4; off >= 1; off >>= 1)
            t += __shfl_xor_sync(0xffffffffu, t, off);
        if (lane == 0) red[0] = t * (1.0f / DD);
    }
    __syncthreads();
    const float rstd = rsqrtf(red[0] + EPSL);

    __half* yr = y + (size_t)row * DD;
#pragma unroll
    for (int i = 0; i < 3; ++i) {
        const int c = tid + i * 256;
        yr[c] = __float2half_rn((vals[i] - mu) * rstd * g[c] + bta[c]);
    }
}

// ---------------- launch ------------------------------------------------------
extern "C" void kernel_launch(void* const* d_in, const int* in_sizes, int n_in,
                              void* d_out, int out_size)
{
    (void)in_sizes; (void)n_in; (void)out_size;
    const float* Q    = (const float*)d_in[0];
    const float* K    = (const float*)d_in[1];
    const float* V    = (const float*)d_in[2];
    const float* Wq   = (const float*)d_in[3];
    const float* bq   = (const float*)d_in[4];
    const float* Wk   = (const float*)d_in[5];
    const float* bk   = (const float*)d_in[6];
    const float* Wv   = (const float*)d_in[7];
    const float* bv   = (const float*)d_in[8];
    const float* Wo   = (const float*)d_in[9];
    const float* bo   = (const float*)d_in[10];
    const float* ln_g = (const float*)d_in[11];
    const float* ln_b = (const float*)d_in[12];
    const float* W1   = (const float*)d_in[13];
    const float* b1   = (const float*)d_in[14];
    const float* W2   = (const float*)d_in[15];
    const float* b2   = (const float*)d_in[16];
    float* out = (float*)d_out;

    __half* hp = nullptr;
    cudaGetSymbolAddress((void**)&hp, g_half);
    float* gx1 = nullptr;
    cudaGetSymbolAddress((void**)&gx1, g_x1);

    __half* qr   = hp + HO_QR;
    __half* kr   = hp + HO_KR;
    __half* vr   = hp + HO_VR;
    __half* gq   = hp + HO_GQ;
    __half* gk   = hp + HO_GK;
    __half* gv   = hp + HO_GV;
    __half* gctx = hp + HO_CTX;
    __half* gh   = hp + HO_H;
    __half* gff  = hp + HO_FF;
    __half* Wqr  = hp + HO_WQ;
    __half* Wkr  = hp + HO_WK;
    __half* Wvr  = hp + HO_WV;
    __half* Wor  = hp + HO_WO;
    __half* W1r  = hp + HO_W1;
    __half* W2r  = hp + HO_W2;

    cudaFuncSetAttribute(attn_h, cudaFuncAttributeMaxDynamicSharedMemorySize,
                         ATTN_SMEM);
    cudaFuncSetAttribute(hgemm<128, 256, 0, 1>,
                         cudaFuncAttributeMaxDynamicSharedMemorySize, GEMM_SMEM_W);
    cudaFuncSetAttribute(hgemm<128, 256, 2, 1>,
                         cudaFuncAttributeMaxDynamicSharedMemorySize, GEMM_SMEM_W);
    cudaFuncSetAttribute(hgemm<64, 128, 1, 0>,
                         cudaFuncAttributeMaxDynamicSharedMemorySize, GEMM_SMEM_N);
    cudaFuncSetAttribute(hgemm<64, 128, 0, 0>,
                         cudaFuncAttributeMaxDynamicSharedMemorySize, GEMM_SMEM_N);

    const dim3 blk(256);

    // merged pre-pass
    {
        Segs S;
        const int nD = SZ_D / 4, nW = SZ_W / 4, nW1 = SZ_W1 / 4;
        S.g[0] = { Q,  qr  }; S.g[1] = { K,  kr  }; S.g[2] = { V,  vr  };
        S.g[3] = { Wq, Wqr }; S.g[4] = { Wk, Wkr }; S.g[5] = { Wv, Wvr };
        S.g[6] = { Wo, Wor }; S.g[7] = { W1, W1r }; S.g[8] = { W2, W2r };
        int c = 0;
        const int lens[9] = { nD, nD, nD, nW, nW, nW, nW, nW1, nW1 };
        for (int j = 0; j < 9; ++j) { S.cum[j] = c; c += lens[j]; }
        S.cum[9] = c;
        f2h_multi<<<c / 256, blk>>>(S);
    }

    // QKV projections (one wide fused launch)
    {
        GSet3 P;
        P.s[0] = { qr, Wqr, bq, nullptr, gq };
        P.s[1] = { kr, Wkr, bk, nullptr, gk };
        P.s[2] = { vr, Wvr, bv, nullptr, gv };
        hgemm<128, 256, 0, 1><<<dim3(DD / 256, MR / 128, 3), blk, GEMM_SMEM_W>>>(
            P, MR, DD, DD);
    }

    // attention (occ 2, split K/V waits)
    attn_h<<<dim3(BB * HH, SS / 128), blk, ATTN_SMEM>>>(gq, gk, gv, gctx);

    // output projection + fp32 residual
    {
        GSet3 P;
        P.s[0] = { gctx, Wor, bo, Q, gx1 };
        P.s[1] = P.s[0]; P.s[2] = P.s[0];
        hgemm<64, 128, 1, 0><<<dim3(DD / 128, MR / 64, 1), dim3(128), GEMM_SMEM_N>>>(
            P, MR, DD, DD);
    }

    // layernorm
    ln_kernel<<<MR, blk>>>(gx1, ln_g, ln_b, gh);

    // FFN1 (wide) + FFN2 (narrow)
    {
        GSet3 P;
        P.s[0] = { gh, W1r, b1, nullptr, gff };
        P.s[1] = P.s[0]; P.s[2] = P.s[0];
        hgemm<128, 256, 2, 1><<<dim3(DFF / 256, MR / 128, 1), blk, GEMM_SMEM_W>>>(
            P, MR, DFF, DD);
    }
    {
        GSet3 P;
        P.s[0] = { gff, W2r, b2, nullptr, out };
        P.s[1] = P.s[0]; P.s[2] = P.s[0];
        hgemm<64, 128, 0, 0><<<dim3(DD / 128, MR / 64, 1), dim3(128), GEMM_SMEM_N>>>(
            P, MR, DD, DFF);
    }
}

// round 16
// speedup vs baseline: 1.0032x; 1.0032x over previous
#include <cuda_runtime.h>
#include <cuda_fp16.h>
#include <math.h>
#include <stdint.h>

// Problem constants
#define BB   4
#define SS   2048
#define DD   768
#define HH   12
#define DFF  3072
#define MR   8192          // B*S
#define EPSL 1e-5f

#define SZ_D   (MR * DD)
#define SZ_FF  (MR * DFF)
#define SZ_W   (DD * DD)
#define SZ_W1  (DD * DFF)

// ---------------- scratch ----------------------------------------------------
static __device__ __align__(256) __half g_half[8 * SZ_D + SZ_FF + 4 * SZ_W + 2 * SZ_W1];
static __device__ __align__(256) float g_x1[SZ_D];

#define HO_QR   0
#define HO_KR   (HO_QR + SZ_D)
#define HO_VR   (HO_KR + SZ_D)
#define HO_GQ   (HO_VR + SZ_D)
#define HO_GK   (HO_GQ + SZ_D)
#define HO_GV   (HO_GK + SZ_D)
#define HO_CTX  (HO_GV + SZ_D)
#define HO_H    (HO_CTX + SZ_D)
#define HO_FF   (HO_H + SZ_D)
#define HO_WQ   (HO_FF + SZ_FF)
#define HO_WK   (HO_WQ + SZ_W)
#define HO_WV   (HO_WK + SZ_W)
#define HO_WO   (HO_WV + SZ_W)
#define HO_W1   (HO_WO + SZ_W)
#define HO_W2   (HO_W1 + SZ_W1)

// ---------------- helpers ----------------------------------------------------
__device__ __forceinline__ float gelu_exact(float x) {
    return 0.5f * x * (1.0f + erff(x * 0.70710678118654752f));
}

__device__ __forceinline__ void cpa16(uint32_t s, const void* g) {
    asm volatile("cp.async.cg.shared.global [%0], [%1], 16;" :: "r"(s), "l"(g));
}

__device__ __forceinline__ uint32_t smem_u32(const void* p) {
    uint32_t a;
    asm("{ .reg .u64 t; cvta.to.shared.u64 t, %1; cvt.u32.u64 %0, t; }"
        : "=r"(a) : "l"(p));
    return a;
}

#define LDSM4(r0, r1, r2, r3, addr)                                            \
    asm volatile("ldmatrix.sync.aligned.m8n8.x4.shared.b16 {%0,%1,%2,%3}, [%4];" \
        : "=r"(r0), "=r"(r1), "=r"(r2), "=r"(r3) : "r"(addr))

#define LDSM4T(r0, r1, r2, r3, addr)                                           \
    asm volatile("ldmatrix.sync.aligned.m8n8.x4.trans.shared.b16 {%0,%1,%2,%3}, [%4];" \
        : "=r"(r0), "=r"(r1), "=r"(r2), "=r"(r3) : "r"(addr))

// fp16 warp MMA: D(16x8,f32) += A(16x16,f16) * B(16x8,f16)
__device__ __forceinline__ void mma16(float* c, const uint32_t* a, const uint32_t* b) {
    asm volatile(
        "mma.sync.aligned.m16n8k16.row.col.f32.f16.f16.f32 "
        "{%0,%1,%2,%3}, {%4,%5,%6,%7}, {%8,%9}, {%0,%1,%2,%3};"
        : "+f"(c[0]), "+f"(c[1]), "+f"(c[2]), "+f"(c[3])
        : "r"(a[0]), "r"(a[1]), "r"(a[2]), "r"(a[3]), "r"(b[0]), "r"(b[1]));
}

__device__ __forceinline__ uint32_t pack2h(float lo, float hi) {
    __half2 h = __floats2half2_rn(lo, hi);
    return *(uint32_t*)&h;
}

// ---------------- merged pre-pass: fp32 -> fp16, 9 segments ------------------
struct Seg  { const float* s; __half* d; };
struct Segs { Seg g[9]; int cum[10]; };

__global__ __launch_bounds__(256) void f2h_multi(Segs S)
{
    const int base = blockIdx.x * 256;
    int seg = 0;
#pragma unroll
    for (int j = 1; j < 9; ++j)
        if (base >= S.cum[j]) seg = j;
    const int i = base - S.cum[seg] + threadIdx.x;
    const float4 v = ((const float4*)S.g[seg].s)[i];
    uint2 o;
    o.x = pack2h(v.x, v.y);
    o.y = pack2h(v.z, v.w);
    ((uint2*)S.g[seg].d)[i] = o;
}

// ---------------- fp16 mma GEMM (unchanged from R10) -------------------------
struct GSet { const __half* A; const __half* Bm; const float* bias;
              const float* res; void* C; };
struct GSet3 { GSet s[3]; };

#define APADH 24
#define NSTG  4

template <int CTAM, int CTAN, int EPI, int OUTH>
__global__ __launch_bounds__((CTAN == 256) ? 256 : 128, (CTAN == 256) ? 1 : 3)
void hgemm(GSet3 P, int M, int N, int K)
{
    constexpr int T     = (CTAN == 256) ? 256 : 128;
    constexpr int MT    = CTAM / 32;
    constexpr int BPADH = CTAN + 8;
    constexpr int ASTG  = CTAM * APADH;
    constexpr int BSTG  = 16 * BPADH;
    constexpr int NQ    = CTAN / 8;

    extern __shared__ __half hsm[];
    __half* As = hsm;
    __half* Bs = hsm + NSTG * ASTG;

    const GSet gs = P.s[blockIdx.z];
    const __half* __restrict__ A = gs.A;
    const __half* __restrict__ Bm = gs.Bm;
    const float* __restrict__ bias = gs.bias;
    const float* __restrict__ res = gs.res;

    const int tid = threadIdx.x;
    const int wid = tid >> 5;
    const int lane = tid & 31;
    const int wm = wid & 1;
    const int wn = wid >> 1;

    const int bm = blockIdx.y * CTAM;
    const int bn = blockIdx.x * CTAN;

    float acc[MT][8][4];
#pragma unroll
    for (int i = 0; i < MT; ++i)
#pragma unroll
        for (int j = 0; j < 8; ++j)
#pragma unroll
            for (int q = 0; q < 4; ++q) acc[i][j][q] = 0.0f;

    const uint32_t sAb = smem_u32(As);
    const uint32_t sBb = smem_u32(Bs);

    const int KT = K >> 4;

    auto load_stage = [&](int kt) {
        const int st = kt & 3;
        const int k0 = kt << 4;
        const uint32_t aB = sAb + (uint32_t)st * ASTG * 2u;
        const uint32_t bB = sBb + (uint32_t)st * BSTG * 2u;
        {
            const int m = tid >> 1, hc = (tid & 1) * 8;
            cpa16(aB + (uint32_t)(m * APADH + hc) * 2u,
                  A + (size_t)(bm + m) * K + k0 + hc);
        }
#pragma unroll
        for (int i = 0; i < 2; ++i) {
            const int c = tid + i * T;
            const int kr = c / NQ, nq = c % NQ;
            cpa16(bB + (uint32_t)(kr * BPADH + nq * 8) * 2u,
                  Bm + (size_t)(k0 + kr) * N + bn + nq * 8);
        }
        asm volatile("cp.async.commit_group;" ::: "memory");
    };

    load_stage(0); load_stage(1); load_stage(2);

    for (int kt = 0; kt < KT; ++kt) {
        const int rem = KT - 1 - kt;
        if (rem >= 2)      asm volatile("cp.async.wait_group 2;" ::: "memory");
        else if (rem == 1) asm volatile("cp.async.wait_group 1;" ::: "memory");
        else               asm volatile("cp.async.wait_group 0;" ::: "memory");
        __syncthreads();
        if (kt + 3 < KT) load_stage(kt + 3);

        const int st = kt & 3;
        const uint32_t aS = sAb + (uint32_t)st * ASTG * 2u;
        const uint32_t bS = sBb + (uint32_t)st * BSTG * 2u;

        uint32_t au[MT][4], bu[8][2];
#pragma unroll
        for (int mt = 0; mt < MT; ++mt) {
            const int row = wm * (CTAM / 2) + mt * 16 + (lane & 15);
            const int kh = (lane >> 4) * 8;
            LDSM4(au[mt][0], au[mt][1], au[mt][2], au[mt][3],
                  aS + (uint32_t)(row * APADH + kh) * 2u);
        }
#pragma unroll
        for (int ng = 0; ng < 4; ++ng) {
            const int n0 = wn * 64 + ng * 16;
            const uint32_t ad = bS +
                (uint32_t)((lane & 15) * BPADH + n0 + (lane >> 4) * 8) * 2u;
            LDSM4T(bu[2 * ng][0], bu[2 * ng][1],
                   bu[2 * ng + 1][0], bu[2 * ng + 1][1], ad);
        }
#pragma unroll
        for (int mt = 0; mt < MT; ++mt)
#pragma unroll
            for (int nt = 0; nt < 8; ++nt)
                mma16(acc[mt][nt], au[mt], bu[nt]);
    }

#pragma unroll
    for (int mt = 0; mt < MT; ++mt) {
        const int r0 = bm + wm * (CTAM / 2) + mt * 16 + (lane >> 2);
#pragma unroll
        for (int nt = 0; nt < 8; ++nt) {
            const int col = bn + wn * 64 + nt * 8 + (lane & 3) * 2;
            const float b0 = bias[col], b1 = bias[col + 1];
            float v0 = acc[mt][nt][0] + b0;
            float v1 = acc[mt][nt][1] + b1;
            float v2 = acc[mt][nt][2] + b0;
            float v3 = acc[mt][nt][3] + b1;
            if (EPI == 1) {
                const float2 ra = *(const float2*)&res[(size_t)r0 * N + col];
                const float2 rb = *(const float2*)&res[(size_t)(r0 + 8) * N + col];
                v0 += ra.x; v1 += ra.y; v2 += rb.x; v3 += rb.y;
            }
            if (EPI == 2) {
                v0 = gelu_exact(v0); v1 = gelu_exact(v1);
                v2 = gelu_exact(v2); v3 = gelu_exact(v3);
            }
            if (OUTH) {
                __half* C = (__half*)gs.C;
                *(uint32_t*)&C[(size_t)r0 * N + col] = pack2h(v0, v1);
                *(uint32_t*)&C[(size_t)(r0 + 8) * N + col] = pack2h(v2, v3);
            } else {
                float* C = (float*)gs.C;
                *(float2*)&C[(size_t)r0 * N + col] = make_float2(v0, v1);
                *(float2*)&C[(size_t)(r0 + 8) * N + col] = make_float2(v2, v3);
            }
        }
    }
}

#define GEMM_SMEM_W ((NSTG * (128 * APADH + 16 * (256 + 8))) * 2)
#define GEMM_SMEM_N ((NSTG * (64 * APADH + 16 * (128 + 8))) * 2)

// ---------------- fp16 flash attention: occ 2, split K/V waits ---------------
#define KPADH 72
#define ATTN_SMEM ((128 * KPADH + 2 * 64 * KPADH + 2 * 64 * KPADH) * 2)

__global__ __launch_bounds__(256, 2) void attn_h(
    const __half* __restrict__ q, const __half* __restrict__ k,
    const __half* __restrict__ v, __half* __restrict__ ctx)
{
    extern __shared__ __half asm_[];
    __half* Qs = asm_;                        // [128][72]
    __half* Ks = Qs + 128 * KPADH;            // [2][64][72]
    __half* Vs = Ks + 2 * 64 * KPADH;         // [2][64][72]

    const int bh = blockIdx.x;
    const int qt = blockIdx.y;
    const int b = bh / HH, h = bh % HH;
    const int tid = threadIdx.x;
    const int wid = tid >> 5;
    const int lane = tid & 31;
    const size_t base = (size_t)(b * SS) * DD + h * 64;
    const int q0 = qt * 128;
    const int NT = SS / 64;

    // stage Q
#pragma unroll
    for (int i = 0; i < 4; ++i) {
        const int idx = tid + i * 256;
        const int r = idx >> 3, hc = idx & 7;
        cpa16(smem_u32(Qs + r * KPADH + hc * 8),
              q + base + (size_t)(q0 + r) * DD + hc * 8);
    }
    asm volatile("cp.async.commit_group; cp.async.wait_group 0;" ::: "memory");
    __syncthreads();

    // Q fragments, scaled by 1/8
    uint32_t qf[4][4];
    {
        const int row = wid * 16 + (lane & 15);
        const __half2 s8 = __float2half2_rn(0.125f);
#pragma unroll
        for (int dk = 0; dk < 4; ++dk) {
            LDSM4(qf[dk][0], qf[dk][1], qf[dk][2], qf[dk][3],
                  smem_u32(Qs + row * KPADH + dk * 16 + (lane >> 4) * 8));
#pragma unroll
            for (int j = 0; j < 4; ++j) {
                __half2 t = __hmul2(*(__half2*)&qf[dk][j], s8);
                qf[dk][j] = *(uint32_t*)&t;
            }
        }
    }

    float oacc[8][4];
#pragma unroll
    for (int nt = 0; nt < 8; ++nt)
#pragma unroll
        for (int i = 0; i < 4; ++i) oacc[nt][i] = 0.0f;
    float m0 = -INFINITY, m1 = -INFINITY, l0 = 0.0f, l1 = 0.0f;

    // prefetch: K and V in SEPARATE commit groups (K first)
    auto prefetch = [&](int t) {
        const int buf = t & 1;
#pragma unroll
        for (int i = 0; i < 2; ++i) {
            const int idx = tid + i * 256;
            const int r = idx >> 3, hc = idx & 7;
            cpa16(smem_u32(Ks + (buf * 64 + r) * KPADH + hc * 8),
                  k + base + (size_t)(t * 64 + r) * DD + hc * 8);
        }
        asm volatile("cp.async.commit_group;" ::: "memory");
#pragma unroll
        for (int i = 0; i < 2; ++i) {
            const int idx = tid + i * 256;
            const int r = idx >> 3, hc = idx & 7;
            cpa16(smem_u32(Vs + (buf * 64 + r) * KPADH + hc * 8),
                  v + base + (size_t)(t * 64 + r) * DD + hc * 8);
        }
        asm volatile("cp.async.commit_group;" ::: "memory");
    };

    prefetch(0);

    for (int t = 0; t < NT; ++t) {
        // K(t) ready (V(t) may still be in flight)
        asm volatile("cp.async.wait_group 1;" ::: "memory");
        __syncthreads();                       // all warps done with buffer t-1
        const bool more = (t + 1 < NT);
        if (more) prefetch(t + 1);             // commits K(t+1), V(t+1)

        const uint32_t kb = smem_u32(Ks + (t & 1) * 64 * KPADH);
        const uint32_t vb = smem_u32(Vs + (t & 1) * 64 * KPADH);

        // S = Q K^T
        float sacc[8][4];
#pragma unroll
        for (int nt = 0; nt < 8; ++nt)
#pragma unroll
            for (int i = 0; i < 4; ++i) sacc[nt][i] = 0.0f;

#pragma unroll
        for (int dk = 0; dk < 4; ++dk) {
            uint32_t ku[8][2];
#pragma unroll
            for (int cg = 0; cg < 4; ++cg) {
                const int row = cg * 16 + (lane & 7) + ((lane >> 4) * 8);
                const int dh = dk * 16 + ((lane >> 3) & 1) * 8;
                LDSM4(ku[2 * cg][0], ku[2 * cg][1],
                      ku[2 * cg + 1][0], ku[2 * cg + 1][1],
                      kb + (uint32_t)(row * KPADH + dh) * 2u);
            }
#pragma unroll
            for (int ct = 0; ct < 8; ++ct) mma16(sacc[ct], qf[dk], ku[ct]);
        }

        // online softmax
        float mx0 = -INFINITY, mx1 = -INFINITY;
#pragma unroll
        for (int nt = 0; nt < 8; ++nt) {
            mx0 = fmaxf(mx0, fmaxf(sacc[nt][0], sacc[nt][1]));
            mx1 = fmaxf(mx1, fmaxf(sacc[nt][2], sacc[nt][3]));
        }
        mx0 = fmaxf(mx0, __shfl_xor_sync(0xffffffffu, mx0, 1));
        mx0 = fmaxf(mx0, __shfl_xor_sync(0xffffffffu, mx0, 2));
        mx1 = fmaxf(mx1, __shfl_xor_sync(0xffffffffu, mx1, 1));
        mx1 = fmaxf(mx1, __shfl_xor_sync(0xffffffffu, mx1, 2));

        const float mn0 = fmaxf(m0, mx0), mn1 = fmaxf(m1, mx1);
        const float cor0 = __expf(m0 - mn0), cor1 = __expf(m1 - mn1);
        float rs0 = 0.0f, rs1 = 0.0f;
#pragma unroll
        for (int nt = 0; nt < 8; ++nt) {
            sacc[nt][0] = __expf(sacc[nt][0] - mn0);
            sacc[nt][1] = __expf(sacc[nt][1] - mn0);
            sacc[nt][2] = __expf(sacc[nt][2] - mn1);
            sacc[nt][3] = __expf(sacc[nt][3] - mn1);
            rs0 += sacc[nt][0] + sacc[nt][1];
            rs1 += sacc[nt][2] + sacc[nt][3];
        }
        rs0 += __shfl_xor_sync(0xffffffffu, rs0, 1);
        rs0 += __shfl_xor_sync(0xffffffffu, rs0, 2);
        rs1 += __shfl_xor_sync(0xffffffffu, rs1, 1);
        rs1 += __shfl_xor_sync(0xffffffffu, rs1, 2);

        l0 = l0 * cor0 + rs0;
        l1 = l1 * cor1 + rs1;
        m0 = mn0; m1 = mn1;
#pragma unroll
        for (int nt = 0; nt < 8; ++nt) {
            oacc[nt][0] *= cor0; oacc[nt][1] *= cor0;
            oacc[nt][2] *= cor1; oacc[nt][3] *= cor1;
        }

        // V(t) ready: if prefetch(t+1) issued, 2 newer groups outstanding
        if (more) { asm volatile("cp.async.wait_group 2;" ::: "memory"); }
        else      { asm volatile("cp.async.wait_group 0;" ::: "memory"); }

        // O += P V  (P in registers)
#pragma unroll
        for (int cc = 0; cc < 4; ++cc) {
            uint32_t af[4];
            af[0] = pack2h(sacc[2 * cc][0], sacc[2 * cc][1]);
            af[1] = pack2h(sacc[2 * cc][2], sacc[2 * cc][3]);
            af[2] = pack2h(sacc[2 * cc + 1][0], sacc[2 * cc + 1][1]);
            af[3] = pack2h(sacc[2 * cc + 1][2], sacc[2 * cc + 1][3]);

            uint32_t vu[8][2];
#pragma unroll
            for (int dg = 0; dg < 4; ++dg) {
                const int row = cc * 16 + (lane & 15);
                const int dh = dg * 16 + (lane >> 4) * 8;
                LDSM4T(vu[2 * dg][0], vu[2 * dg][1],
                       vu[2 * dg + 1][0], vu[2 * dg + 1][1],
                       vb + (uint32_t)(row * KPADH + dh) * 2u);
            }
#pragma unroll
            for (int dt = 0; dt < 8; ++dt) mma16(oacc[dt], af, vu[dt]);
        }
    }

    const float inv0 = 1.0f / l0, inv1 = 1.0f / l1;
    const int row0 = wid * 16 + (lane >> 2);
#pragma unroll
    for (int dt = 0; dt < 8; ++dt) {
        const int col = dt * 8 + (lane & 3) * 2;
        *(uint32_t*)(ctx + base + (size_t)(q0 + row0) * DD + col) =
            pack2h(oacc[dt][0] * inv0, oacc[dt][1] * inv0);
        *(uint32_t*)(ctx + base + (size_t)(q0 + row0 + 8) * DD + col) =
            pack2h(oacc[dt][2] * inv1, oacc[dt][3] * inv1);
    }
}

// ---------------- layernorm: fp32 in, half out -------------------------------
__global__ __launch_bounds__(256) void ln_kernel(
    const float* __restrict__ x, const float* __restrict__ g,
    const float* __restrict__ bta, __half* __restrict__ y)
{
    const int row = blockIdx.x;
    const float* xr = x + (size_t)row * DD;
    const int tid = threadIdx.x;
    const int lane = tid & 31;
    const int wid = tid >> 5;

    float vals[3];
#pragma unroll
    for (int i = 0; i < 3; ++i) vals[i] = xr[tid + i * 256];

    __shared__ float red[32];

    float sum = vals[0] + vals[1] + vals[2];
#pragma unroll
    for (int off = 16; off >= 1; off >>= 1)
        sum += __shfl_xor_sync(0xffffffffu, sum, off);
    if (lane == 0) red[wid] = sum;
    __syncthreads();
    if (tid < 32) {
        float t = (lane < 8) ? red[lane] : 0.0f;
#pragma unroll
        for (int off = 4; off >= 1; off >>= 1)
            t += __shfl_xor_sync(0xffffffffu, t, off);
        if (lane == 0) red[0] = t * (1.0f / DD);
    }
    __syncthreads();
    const float mu = red[0];
    __syncthreads();

    float vs = 0.0f;
#pragma unroll
    for (int i = 0; i < 3; ++i) {
        const float d = vals[i] - mu;
        vs += d * d;
    }
#pragma unroll
    for (int off = 16; off >= 1; off >>= 1)
        vs += __shfl_xor_sync(0xffffffffu, vs, off);
    if (lane == 0) red[wid] = vs;
    __syncthreads();
    if (tid < 32) {
        float t = (lane < 8) ? red[lane] : 0.0f;
#pragma unroll
        for (int off = 4; off >= 1; off >>= 1)
            t += __shfl_xor_sync(0xffffffffu, t, off);
        if (lane == 0) red[0] = t * (1.0f / DD);
    }
    __syncthreads();
    const float rstd = rsqrtf(red[0] + EPSL);

    __half* yr = y + (size_t)row * DD;
#pragma unroll
    for (int i = 0; i < 3; ++i) {
        const int c = tid + i * 256;
        yr[c] = __float2half_rn((vals[i] - mu) * rstd * g[c] + bta[c]);
    }
}

// ---------------- launch ------------------------------------------------------
extern "C" void kernel_launch(void* const* d_in, const int* in_sizes, int n_in,
                              void* d_out, int out_size)
{
    (void)in_sizes; (void)n_in; (void)out_size;
    const float* Q    = (const float*)d_in[0];
    const float* K    = (const float*)d_in[1];
    const float* V    = (const float*)d_in[2];
    const float* Wq   = (const float*)d_in[3];
    const float* bq   = (const float*)d_in[4];
    const float* Wk   = (const float*)d_in[5];
    const float* bk   = (const float*)d_in[6];
    const float* Wv   = (const float*)d_in[7];
    const float* bv   = (const float*)d_in[8];
    const float* Wo   = (const float*)d_in[9];
    const float* bo   = (const float*)d_in[10];
    const float* ln_g = (const float*)d_in[11];
    const float* ln_b = (const float*)d_in[12];
    const float* W1   = (const float*)d_in[13];
    const float* b1   = (const float*)d_in[14];
    const float* W2   = (const float*)d_in[15];
    const float* b2   = (const float*)d_in[16];
    float* out = (float*)d_out;

    __half* hp = nullptr;
    cudaGetSymbolAddress((void**)&hp, g_half);
    float* gx1 = nullptr;
    cudaGetSymbolAddress((void**)&gx1, g_x1);

    __half* qr   = hp + HO_QR;
    __half* kr   = hp + HO_KR;
    __half* vr   = hp + HO_VR;
    __half* gq   = hp + HO_GQ;
    __half* gk   = hp + HO_GK;
    __half* gv   = hp + HO_GV;
    __half* gctx = hp + HO_CTX;
    __half* gh   = hp + HO_H;
    __half* gff  = hp + HO_FF;
    __half* Wqr  = hp + HO_WQ;
    __half* Wkr  = hp + HO_WK;
    __half* Wvr  = hp + HO_WV;
    __half* Wor  = hp + HO_WO;
    __half* W1r  = hp + HO_W1;
    __half* W2r  = hp + HO_W2;

    cudaFuncSetAttribute(attn_h, cudaFuncAttributeMaxDynamicSharedMemorySize,
                         ATTN_SMEM);
    cudaFuncSetAttribute(hgemm<128, 256, 0, 1>,
                         cudaFuncAttributeMaxDynamicSharedMemorySize, GEMM_SMEM_W);
    cudaFuncSetAttribute(hgemm<128, 256, 2, 1>,
                         cudaFuncAttributeMaxDynamicSharedMemorySize, GEMM_SMEM_W);
    cudaFuncSetAttribute(hgemm<64, 128, 1, 0>,
                         cudaFuncAttributeMaxDynamicSharedMemorySize, GEMM_SMEM_N);
    cudaFuncSetAttribute(hgemm<64, 128, 0, 0>,
                         cudaFuncAttributeMaxDynamicSharedMemorySize, GEMM_SMEM_N);

    const dim3 blk(256);

    // merged pre-pass
    {
        Segs S;
        const int nD = SZ_D / 4, nW = SZ_W / 4, nW1 = SZ_W1 / 4;
        S.g[0] = { Q,  qr  }; S.g[1] = { K,  kr  }; S.g[2] = { V,  vr  };
        S.g[3] = { Wq, Wqr }; S.g[4] = { Wk, Wkr }; S.g[5] = { Wv, Wvr };
        S.g[6] = { Wo, Wor }; S.g[7] = { W1, W1r }; S.g[8] = { W2, W2r };
        int c = 0;
        const int lens[9] = { nD, nD, nD, nW, nW, nW, nW, nW1, nW1 };
        for (int j = 0; j < 9; ++j) { S.cum[j] = c; c += lens[j]; }
        S.cum[9] = c;
        f2h_multi<<<c / 256, blk>>>(S);
    }

    // QKV projections (one wide fused launch)
    {
        GSet3 P;
        P.s[0] = { qr, Wqr, bq, nullptr, gq };
        P.s[1] = { kr, Wkr, bk, nullptr, gk };
        P.s[2] = { vr, Wvr, bv, nullptr, gv };
        hgemm<128, 256, 0, 1><<<dim3(DD / 256, MR / 128, 3), blk, GEMM_SMEM_W>>>(
            P, MR, DD, DD);
    }

    // attention (occ 2, split K/V waits)
    attn_h<<<dim3(BB * HH, SS / 128), blk, ATTN_SMEM>>>(gq, gk, gv, gctx);

    // output projection + fp32 residual
    {
        GSet3 P;
        P.s[0] = { gctx, Wor, bo, Q, gx1 };
        P.s[1] = P.s[0]; P.s[2] = P.s[0];
        hgemm<64, 128, 1, 0><<<dim3(DD / 128, MR / 64, 1), dim3(128), GEMM_SMEM_N>>>(
            P, MR, DD, DD);
    }

    // layernorm
    ln_kernel<<<MR, blk>>>(gx1, ln_g, ln_b, gh);

    // FFN1 (wide) + FFN2 (narrow)
    {
        GSet3 P;
        P.s[0] = { gh, W1r, b1, nullptr, gff };
        P.s[1] = P.s[0]; P.s[2] = P.s[0];
        hgemm<128, 256, 2, 1><<<dim3(DFF / 256, MR / 128, 1), blk, GEMM_SMEM_W>>>(
            P, MR, DFF, DD);
    }
    {
        GSet3 P;
        P.s[0] = { gff, W2r, b2, nullptr, out };
        P.s[1] = P.s[0]; P.s[2] = P.s[0];
        hgemm<64, 128, 0, 0><<<dim3(DD / 128, MR / 64, 1), dim3(128), GEMM_SMEM_N>>>(
            P, MR, DD, DFF);
    }
}